// round 2
// baseline (speedup 1.0000x reference)
#include <cuda_runtime.h>
#include <math.h>

#define NP   8192
#define DIM  128
#define BM   64
#define BN   64
#define NTILES (NP / BN)

#define CURVF  0.05f
#define CURV2F 0.0025f
#define SQRTCF 0.22360679774997896f
#define KLN2F  6.1996966f            // K * ln2, K = 1/(sqrt_c * T) = 8.944272
#define KFULLF 8.944271909999159f
#define TEMPF  0.5f

// scratch (device globals: allocation-free)
__device__ float  g_f[NP * DIM];
__device__ float  g_n2[NP];
__device__ float4 g_stats[NP];   // x=Sum_pos exp, y=Sum_neg exp, z=Sum_pos adc, w=num_pos

__device__ __forceinline__ float f_rcp(float x){float r;asm("rcp.approx.f32 %0,%1;":"=f"(r):"f"(x));return r;}
__device__ __forceinline__ float f_rsq(float x){float r;asm("rsqrt.approx.f32 %0,%1;":"=f"(r):"f"(x));return r;}
__device__ __forceinline__ float f_lg2(float x){float r;asm("lg2.approx.f32 %0,%1;":"=f"(r):"f"(x));return r;}
__device__ __forceinline__ float f_ex2(float x){float r;asm("ex2.approx.f32 %0,%1;":"=f"(r):"f"(x));return r;}

// ---------------------------------------------------------------------------
// Kernel 1: row-normalize features, produce g_f (normalized) and g_n2 (=|f|^2)
// One warp per row: 32 lanes x float4 = 128 elements.
__global__ void norm_kernel(const float* __restrict__ feat) {
    int row  = blockIdx.x * 8 + (threadIdx.x >> 5);
    int lane = threadIdx.x & 31;
    float4 v = ((const float4*)(feat + row * DIM))[lane];
    float s = v.x*v.x + v.y*v.y + v.z*v.z + v.w*v.w;
    #pragma unroll
    for (int o = 16; o; o >>= 1) s += __shfl_xor_sync(0xffffffffu, s, o);
    float nrm = fmaxf(sqrtf(s), 1e-12f);
    float inv = 1.0f / nrm;
    float4 o4 = make_float4(v.x*inv, v.y*inv, v.z*inv, v.w*inv);
    ((float4*)(g_f + row * DIM))[lane] = o4;
    if (lane == 0) g_n2[row] = s * inv * inv;
}

// ---------------------------------------------------------------------------
// Kernel 2: fused GEMM (s = f f^T tile) + hyperbolic distance + masked row sums.
// Block = 64-row stripe, loops over all 128 column tiles of 64.
// smem layout (dynamic): As[128][64], Bs[128][64] (k-major, XOR-swizzled in
// float4 words), then col metadata arrays.
__global__ void __launch_bounds__(256)
pair_kernel(const int* __restrict__ pl, const int* __restrict__ sl) {
    extern __shared__ float smem[];
    float* As  = smem;                 // DIM*BM
    float* Bs  = As + DIM * BM;        // DIM*BN
    float* n2c = Bs + DIM * BN;        // BN
    float* Bcn = n2c + BN;             // BN : B = 1 - c*x2
    float* bbc = Bcn + BN;             // BN : B*B
    int*   plc = (int*)(bbc + BN);     // BN
    int*   slc = plc + BN;             // BN

    const int tid = threadIdx.x;
    const int tx  = tid & 15;          // col group (4 cols)
    const int ty  = tid >> 4;          // row group (4 rows)
    const int i0  = blockIdx.x * BM;

    // Load A stripe once: element (k, r) -> As[k*BM + swz]
    for (int idx = tid; idx < BM * DIM; idx += 256) {
        int k = idx & (DIM - 1);
        int r = idx >> 7;
        As[k * BM + ((((r >> 2) ^ (k & 15)) << 2) | (r & 3))] = g_f[i0 * DIM + idx];
    }

    // Row constants
    float y2[4], Ay[4], cyc[4];
    int pli[4], sli[4];
    #pragma unroll
    for (int rr = 0; rr < 4; rr++) {
        int gi = i0 + ty * 4 + rr;
        float n2v = g_n2[gi];
        y2[rr]  = n2v;
        Ay[rr]  = fmaf(CURVF, n2v, 1.0f);
        cyc[rr] = CURV2F * n2v;
        pli[rr] = pl[gi];
        sli[rr] = sl[gi];
    }

    float Sp[4] = {0,0,0,0}, Sn[4] = {0,0,0,0}, Ap[4] = {0,0,0,0}, Npo[4] = {0,0,0,0};

    for (int t = 0; t < NTILES; t++) {
        const int j0 = t * BN;
        __syncthreads();   // previous tile's consumers done before overwrite
        for (int idx = tid; idx < BN * DIM; idx += 256) {
            int k = idx & (DIM - 1);
            int r = idx >> 7;
            Bs[k * BN + ((((r >> 2) ^ (k & 15)) << 2) | (r & 3))] = g_f[j0 * DIM + idx];
        }
        if (tid < BN) {
            int gj = j0 + tid;
            float x2 = g_n2[gj];
            float B  = fmaf(-CURVF, x2, 1.0f);
            n2c[tid] = x2; Bcn[tid] = B; bbc[tid] = B * B;
            plc[tid] = pl[gj]; slc[tid] = sl[gj];
        }
        __syncthreads();

        float acc[4][4];
        #pragma unroll
        for (int a = 0; a < 4; a++)
            #pragma unroll
            for (int b = 0; b < 4; b++) acc[a][b] = 0.0f;

        #pragma unroll 16
        for (int k = 0; k < DIM; k++) {
            const float4 av = *(const float4*)&As[k * BM + ((ty ^ (k & 15)) << 2)];
            const float4 bv = *(const float4*)&Bs[k * BN + ((tx ^ (k & 15)) << 2)];
            acc[0][0] = fmaf(av.x, bv.x, acc[0][0]);
            acc[0][1] = fmaf(av.x, bv.y, acc[0][1]);
            acc[0][2] = fmaf(av.x, bv.z, acc[0][2]);
            acc[0][3] = fmaf(av.x, bv.w, acc[0][3]);
            acc[1][0] = fmaf(av.y, bv.x, acc[1][0]);
            acc[1][1] = fmaf(av.y, bv.y, acc[1][1]);
            acc[1][2] = fmaf(av.y, bv.z, acc[1][2]);
            acc[1][3] = fmaf(av.y, bv.w, acc[1][3]);
            acc[2][0] = fmaf(av.z, bv.x, acc[2][0]);
            acc[2][1] = fmaf(av.z, bv.y, acc[2][1]);
            acc[2][2] = fmaf(av.z, bv.z, acc[2][2]);
            acc[2][3] = fmaf(av.z, bv.w, acc[2][3]);
            acc[3][0] = fmaf(av.w, bv.x, acc[3][0]);
            acc[3][1] = fmaf(av.w, bv.y, acc[3][1]);
            acc[3][2] = fmaf(av.w, bv.z, acc[3][2]);
            acc[3][3] = fmaf(av.w, bv.w, acc[3][3]);
        }

        // Elementwise hyperbolic distance + masked accumulation
        #pragma unroll
        for (int cc = 0; cc < 4; cc++) {
            const int jc = tx * 4 + cc;
            const int gj = j0 + jc;
            const float x2  = n2c[jc];
            const float Bv  = Bcn[jc];
            const float bb  = bbc[jc];
            const int   plj = plc[jc];
            const int   slj = slc[jc];
            #pragma unroll
            for (int rr = 0; rr < 4; rr++) {
                float s   = acc[rr][cc];
                float xy2 = -(s + s);                                // 2*xy
                float A   = fmaf(xy2, CURVF, Ay[rr]);                // 1+2c*xy+c*y2
                float den = fmaf(xy2, CURVF, fmaf(x2, cyc[rr], 1.0f));
                den = fmaxf(den, 1e-15f);
                float tt  = fmaf(A, x2, Bv * xy2);                   // A*x2 + 2B*xy
                float num = fmaf(bb, y2[rr], A * tt);                // A^2 x2 + 2ABxy + B^2 y2
                num = fmaxf(num, 1e-35f);
                float sq = num * f_rsq(num);                         // sqrt(num)
                float nd = SQRTCF * sq * f_rcp(den);
                nd = fminf(nd, 0.9999999f);
                float L2  = f_lg2((1.0f + nd) * f_rcp(1.0f - nd));   // lg2 of atanh ratio
                float adc = -KLN2F * L2;                             // -dist/T (m=0)
                float e   = f_ex2(-KFULLF * L2);                     // exp(adc)
                int gi = i0 + ty * 4 + rr;
                bool samep = (pli[rr] == plj) | (sli[rr] == slj);
                float ppos = (samep && (gi != gj)) ? 1.0f : 0.0f;
                float pneg = samep ? 0.0f : 1.0f;
                Sp[rr]  = fmaf(ppos, e,   Sp[rr]);
                Sn[rr]  = fmaf(pneg, e,   Sn[rr]);
                Ap[rr]  = fmaf(ppos, adc, Ap[rr]);
                Npo[rr] += ppos;
            }
        }
    }

    // Reduce across the 16 col-group threads sharing each row (width-16 shfl)
    #pragma unroll
    for (int rr = 0; rr < 4; rr++) {
        float a = Sp[rr], b = Sn[rr], c2 = Ap[rr], d = Npo[rr];
        #pragma unroll
        for (int o = 8; o; o >>= 1) {
            a  += __shfl_down_sync(0xffffffffu, a,  o, 16);
            b  += __shfl_down_sync(0xffffffffu, b,  o, 16);
            c2 += __shfl_down_sync(0xffffffffu, c2, o, 16);
            d  += __shfl_down_sync(0xffffffffu, d,  o, 16);
        }
        if (tx == 0) g_stats[i0 + ty * 4 + rr] = make_float4(a, b, c2, d);
    }
}

// ---------------------------------------------------------------------------
// Kernel 3: row stats -> scalar loss
__global__ void finalize_kernel(float* __restrict__ out) {
    __shared__ float ssum[32], scnt[32];
    int tid = threadIdx.x;  // 1024 threads
    float sum = 0.0f, nv = 0.0f;
    for (int i = tid; i < NP; i += 1024) {
        float4 st = g_stats[i];
        if (st.w > 0.0f) {
            float den = st.x + st.y + 1e-8f;
            sum += (st.z - st.w * __logf(den)) / st.w;
            nv  += 1.0f;
        }
    }
    #pragma unroll
    for (int o = 16; o; o >>= 1) {
        sum += __shfl_xor_sync(0xffffffffu, sum, o);
        nv  += __shfl_xor_sync(0xffffffffu, nv,  o);
    }
    if ((tid & 31) == 0) { ssum[tid >> 5] = sum; scnt[tid >> 5] = nv; }
    __syncthreads();
    if (tid < 32) {
        sum = ssum[tid]; nv = scnt[tid];
        #pragma unroll
        for (int o = 16; o; o >>= 1) {
            sum += __shfl_xor_sync(0xffffffffu, sum, o);
            nv  += __shfl_xor_sync(0xffffffffu, nv,  o);
        }
        if (tid == 0) {
            float loss = 0.0f;
            if (nv > 0.0f) loss = -sum / fmaxf(nv, 1.0f) * TEMPF;
            if (!isfinite(loss)) loss = 0.0f;
            out[0] = loss;
        }
    }
}

// ---------------------------------------------------------------------------
extern "C" void kernel_launch(void* const* d_in, const int* in_sizes, int n_in,
                              void* d_out, int out_size) {
    const float* feat = (const float*)d_in[0];
    const int*   pl   = (const int*)d_in[1];
    const int*   sl   = (const int*)d_in[2];
    float* out = (float*)d_out;

    const int smem_bytes = (DIM*BM + DIM*BN + 3*BN) * (int)sizeof(float)
                         + 2*BN * (int)sizeof(int);   // 66816 B
    cudaFuncSetAttribute(pair_kernel, cudaFuncAttributeMaxDynamicSharedMemorySize,
                         smem_bytes);

    norm_kernel<<<NP / 8, 256>>>(feat);
    pair_kernel<<<NP / BM, 256, smem_bytes>>>(pl, sl);
    finalize_kernel<<<1, 1024>>>(out);
}

// round 4
// speedup vs baseline: 4.3818x; 4.3818x over previous
#include <cuda_runtime.h>
#include <cuda_bf16.h>
#include <math.h>
#include <stdint.h>

#define NP   8192
#define DIM  128
#define TM   128
#define TN   128
#define NSTRIPES (NP / TM)    // 64
#define TILES 32              // col tiles per CTA (half of 64)

#define SQRTCF 0.22360679774997896f
#define KLN2F  6.1996966f             // (1/(sqrt_c*T)) * ln2
#define KFULLF 8.944271909999159f     // 1/(sqrt_c*T)
#define TEMPF  0.5f

// SMEM tile row stride: 128 bf16 + 8 pad = 136 bf16 = 272 bytes (16B aligned,
// bank-shift 4 per row -> conflict-free ldmatrix & cp.async stores)
#define LDS_ROW 272

#define OFF_A     0
#define OFF_B0    34816
#define OFF_B1    69632
#define OFF_LAB   104448            // int [2][128]
#define OFF_STAT  105472            // float4 [128]
#define SMEM_REQ  (105472 + 2048)

__device__ __nv_bfloat16 g_fb[NP * DIM];   // normalized features, bf16
__device__ float4 g_stats[2 * NP];         // [half][row]: Sp, Sn, Ap, Np

// ---------------- PTX helpers (all valid on base sm_103 target) ----------------
__device__ __forceinline__ uint32_t smem_u32(const void* p) {
    uint32_t a;
    asm("{ .reg .u64 t; cvta.to.shared.u64 t, %1; cvt.u32.u64 %0, t; }" : "=r"(a) : "l"(p));
    return a;
}
__device__ __forceinline__ float f_rcp(float x){float r;asm("rcp.approx.f32 %0,%1;":"=f"(r):"f"(x));return r;}
__device__ __forceinline__ float f_rsq(float x){float r;asm("rsqrt.approx.f32 %0,%1;":"=f"(r):"f"(x));return r;}
__device__ __forceinline__ float f_lg2(float x){float r;asm("lg2.approx.f32 %0,%1;":"=f"(r):"f"(x));return r;}
__device__ __forceinline__ float f_ex2(float x){float r;asm("ex2.approx.f32 %0,%1;":"=f"(r):"f"(x));return r;}

__device__ __forceinline__ void cp16(uint32_t dst, const void* src) {
    asm volatile("cp.async.cg.shared.global [%0], [%1], 16;" :: "r"(dst), "l"(src) : "memory");
}
#define CP_COMMIT() asm volatile("cp.async.commit_group;" ::: "memory")
#define CP_WAIT(n)  asm volatile("cp.async.wait_group %0;" :: "n"(n) : "memory")

__device__ __forceinline__ void ldsm4(uint32_t& r0, uint32_t& r1, uint32_t& r2, uint32_t& r3,
                                      uint32_t addr) {
    asm volatile("ldmatrix.sync.aligned.m8n8.x4.shared.b16 {%0,%1,%2,%3}, [%4];"
                 : "=r"(r0), "=r"(r1), "=r"(r2), "=r"(r3) : "r"(addr));
}
__device__ __forceinline__ void mma16816(float* c, const uint32_t* a, const uint32_t* b) {
    asm volatile(
        "mma.sync.aligned.m16n8k16.row.col.f32.bf16.bf16.f32 "
        "{%0,%1,%2,%3}, {%4,%5,%6,%7}, {%8,%9}, {%0,%1,%2,%3};"
        : "+f"(c[0]), "+f"(c[1]), "+f"(c[2]), "+f"(c[3])
        : "r"(a[0]), "r"(a[1]), "r"(a[2]), "r"(a[3]), "r"(b[0]), "r"(b[1]));
}

// ---------------------------------------------------------------------------
__global__ void norm_kernel(const float* __restrict__ feat) {
    int row  = blockIdx.x * 8 + (threadIdx.x >> 5);
    int lane = threadIdx.x & 31;
    float4 v = ((const float4*)(feat + row * DIM))[lane];
    float s = v.x*v.x + v.y*v.y + v.z*v.z + v.w*v.w;
    #pragma unroll
    for (int o = 16; o; o >>= 1) s += __shfl_xor_sync(0xffffffffu, s, o);
    float inv = 1.0f / fmaxf(sqrtf(s), 1e-12f);
    __nv_bfloat162 p0 = __floats2bfloat162_rn(v.x*inv, v.y*inv);
    __nv_bfloat162 p1 = __floats2bfloat162_rn(v.z*inv, v.w*inv);
    uint2 w;
    w.x = *reinterpret_cast<uint32_t*>(&p0);
    w.y = *reinterpret_cast<uint32_t*>(&p1);
    ((uint2*)g_fb)[row * 32 + lane] = w;
}

// ---------------------------------------------------------------------------
// cp.async one 128x128 bf16 tile (256B rows in GMEM) into padded SMEM.
__device__ __forceinline__ void cp_tile(uint32_t udst, const char* gsrc, int tid) {
    #pragma unroll
    for (int it = 0; it < 8; it++) {
        int idx = tid + it * 256;     // 0..2047
        int row = idx >> 4;
        int ch  = idx & 15;
        cp16(udst + row * LDS_ROW + ch * 16, gsrc + row * 256 + ch * 16);
    }
}

__global__ void __launch_bounds__(256, 1)
pair_kernel(const int* __restrict__ pl, const int* __restrict__ sl) {
    extern __shared__ __align__(16) char sm[];
    const uint32_t ub = smem_u32(sm);

    const int tid  = threadIdx.x;
    const int wid  = tid >> 5;
    const int lane = tid & 31;
    const int wm   = wid & 3;       // warp row block (32 rows)
    const int wn   = wid >> 2;      // warp col block (64 cols)

    const int stripe = blockIdx.x & (NSTRIPES - 1);
    const int half   = blockIdx.x >> 6;
    const int i0     = stripe * TM;
    const int jbase  = half * TILES;

    int*    lab   = (int*)(sm + OFF_LAB);
    float4* sstat = (float4*)(sm + OFF_STAT);
    const char* gsrc = (const char*)g_fb;

    // Prologue: A stripe + B tile 0 + labels 0
    cp_tile(ub + OFF_A,  gsrc + (size_t)i0 * 256, tid);
    {
        int j0 = jbase * TN;
        cp_tile(ub + OFF_B0, gsrc + (size_t)j0 * 256, tid);
        if (tid < 128) lab[tid] = (pl[j0 + tid] << 16) | (sl[j0 + tid] & 0xFFFF);
    }
    CP_COMMIT();

    // Row identity: this thread's 4 accumulator rows
    int girow[4], pk_i[4];
    {
        int base = i0 + wm * 32 + (lane >> 2);
        #pragma unroll
        for (int rr = 0; rr < 4; rr++) {
            int gi = base + (rr >> 1) * 16 + (rr & 1) * 8;
            girow[rr] = gi;
            pk_i[rr]  = (pl[gi] << 16) | (sl[gi] & 0xFFFF);
        }
    }

    // ldmatrix per-lane address offsets (relative to tile base)
    const int g  = lane >> 3;
    const int lr = lane & 7;
    // A x4: matrices (m0-7,k0),(m8-15,k0),(m0-7,k8),(m8-15,k8)
    uint32_t aoff[2];
    #pragma unroll
    for (int a = 0; a < 2; a++)
        aoff[a] = (uint32_t)((wm * 32 + a * 16 + (g & 1) * 8 + lr) * LDS_ROW + (g >> 1) * 16);
    // B x4 (pair p covers n-atoms 2p,2p+1): matrices (n0-7,k0),(n0-7,k8),(n8-15,k0),(n8-15,k8)
    uint32_t boff[4];
    #pragma unroll
    for (int p = 0; p < 4; p++)
        boff[p] = (uint32_t)((wn * 64 + p * 16 + (g >> 1) * 8 + lr) * LDS_ROW + (g & 1) * 16);

    CP_WAIT(0);
    __syncthreads();

    float Sp[4] = {0,0,0,0}, Sn[4] = {0,0,0,0}, Ap[4] = {0,0,0,0}, Npo[4] = {0,0,0,0};

    for (int t = 0; t < TILES; t++) {
        const int cur = t & 1;
        if (t > 0) __syncthreads();           // everyone done reading nb-buffers
        if (t + 1 < TILES) {
            const int nb = (t + 1) & 1;
            const int jn = (jbase + t + 1) * TN;
            cp_tile(ub + (nb ? OFF_B1 : OFF_B0), gsrc + (size_t)jn * 256, tid);
            CP_COMMIT();
            if (tid < 128) lab[nb * 128 + tid] = (pl[jn + tid] << 16) | (sl[jn + tid] & 0xFFFF);
            CP_WAIT(1);
        } else {
            CP_WAIT(0);
        }
        __syncthreads();                      // cur tile visible to all

        const uint32_t uB = ub + (cur ? OFF_B1 : OFF_B0);
        const uint32_t uA = ub + OFF_A;

        float acc[2][8][4];
        #pragma unroll
        for (int a = 0; a < 2; a++)
            #pragma unroll
            for (int b = 0; b < 8; b++)
                #pragma unroll
                for (int j = 0; j < 4; j++) acc[a][b][j] = 0.0f;

        #pragma unroll
        for (int ks = 0; ks < 8; ks++) {
            const uint32_t kb = (uint32_t)(ks * 32);
            uint32_t af[2][4], bf[8][2];
            #pragma unroll
            for (int a = 0; a < 2; a++)
                ldsm4(af[a][0], af[a][1], af[a][2], af[a][3], uA + aoff[a] + kb);
            #pragma unroll
            for (int p = 0; p < 4; p++)
                ldsm4(bf[2*p][0], bf[2*p][1], bf[2*p+1][0], bf[2*p+1][1], uB + boff[p] + kb);
            #pragma unroll
            for (int a = 0; a < 2; a++)
                #pragma unroll
                for (int b = 0; b < 8; b++)
                    mma16816(acc[a][b], af[a], bf[b]);
        }

        // Epilogue: hyperbolic distance + masked accumulation, all in registers
        const int jt = (jbase + t) * TN;
        const int cb = jt + wn * 64 + ((lane & 3) << 1);
        const int* labc = lab + cur * 128;
        #pragma unroll
        for (int b = 0; b < 8; b++) {
            const int c0   = cb + b * 8;
            const int li   = wn * 64 + b * 8 + ((lane & 3) << 1);
            const int pkj0 = labc[li];
            const int pkj1 = labc[li + 1];
            #pragma unroll
            for (int a = 0; a < 2; a++) {
                #pragma unroll
                for (int j = 0; j < 4; j++) {
                    const int rr  = a * 2 + (j >> 1);
                    const int col = c0 + (j & 1);
                    const int pkj = (j & 1) ? pkj1 : pkj0;
                    float sv = acc[a][b][j];
                    float A  = fmaf(-0.1f, sv, 1.05f);
                    float dn = fmaf(-0.1f, sv, 1.0025f);
                    float num = fmaf(A, fmaf(-1.9f, sv, A), 0.9025f);
                    num = fmaxf(num, 1e-30f);
                    float x  = SQRTCF * (num * f_rsq(num));     // sqrt_c * sqrt(num)
                    float r2 = fmaxf(dn - x, 1e-7f * dn);       // clip nd <= 1-1e-7
                    float L2 = f_lg2((dn + x) * f_rcp(r2));
                    float adc = -KLN2F * L2;
                    float e   = f_ex2(-KFULLF * L2);
                    int  dx   = pk_i[rr] ^ pkj;
                    bool samep = ((dx & 0xFFFF0000) == 0) | ((dx & 0xFFFF) == 0);
                    bool isdg  = (col == girow[rr]);
                    float fp = (samep && !isdg) ? 1.0f : 0.0f;
                    float fn = samep ? 0.0f : 1.0f;
                    Sp[rr]  = fmaf(fp, e, Sp[rr]);
                    Sn[rr]  = fmaf(fn, e, Sn[rr]);
                    Ap[rr]  = fmaf(fp, adc, Ap[rr]);
                    Npo[rr] += fp;
                }
            }
        }
    }

    // Reduce across the 4 lanes (l%4) sharing each row
    #pragma unroll
    for (int rr = 0; rr < 4; rr++) {
        #pragma unroll
        for (int o = 1; o <= 2; o <<= 1) {
            Sp[rr]  += __shfl_xor_sync(0xffffffffu, Sp[rr],  o);
            Sn[rr]  += __shfl_xor_sync(0xffffffffu, Sn[rr],  o);
            Ap[rr]  += __shfl_xor_sync(0xffffffffu, Ap[rr],  o);
            Npo[rr] += __shfl_xor_sync(0xffffffffu, Npo[rr], o);
        }
    }
    __syncthreads();
    if (wn == 0 && (lane & 3) == 0) {
        #pragma unroll
        for (int rr = 0; rr < 4; rr++) {
            int rloc = wm * 32 + (rr >> 1) * 16 + (rr & 1) * 8 + (lane >> 2);
            sstat[rloc] = make_float4(Sp[rr], Sn[rr], Ap[rr], Npo[rr]);
        }
    }
    __syncthreads();
    if (wn == 1 && (lane & 3) == 0) {
        #pragma unroll
        for (int rr = 0; rr < 4; rr++) {
            int rloc = wm * 32 + (rr >> 1) * 16 + (rr & 1) * 8 + (lane >> 2);
            float4 v = sstat[rloc];
            v.x += Sp[rr]; v.y += Sn[rr]; v.z += Ap[rr]; v.w += Npo[rr];
            sstat[rloc] = v;
        }
    }
    __syncthreads();
    if (tid < 128) g_stats[half * NP + i0 + tid] = sstat[tid];
}

// ---------------------------------------------------------------------------
__global__ void finalize_kernel(float* __restrict__ out) {
    __shared__ float ssum[32], scnt[32];
    int tid = threadIdx.x;  // 1024
    float sum = 0.0f, nv = 0.0f;
    for (int i = tid; i < NP; i += 1024) {
        float4 a = g_stats[i];
        float4 b = g_stats[NP + i];
        float np = a.w + b.w;
        if (np > 0.0f) {
            float den = a.x + b.x + a.y + b.y + 1e-8f;
            sum += (a.z + b.z - np * __logf(den)) / np;
            nv  += 1.0f;
        }
    }
    #pragma unroll
    for (int o = 16; o; o >>= 1) {
        sum += __shfl_xor_sync(0xffffffffu, sum, o);
        nv  += __shfl_xor_sync(0xffffffffu, nv,  o);
    }
    if ((tid & 31) == 0) { ssum[tid >> 5] = sum; scnt[tid >> 5] = nv; }
    __syncthreads();
    if (tid < 32) {
        sum = ssum[tid]; nv = scnt[tid];
        #pragma unroll
        for (int o = 16; o; o >>= 1) {
            sum += __shfl_xor_sync(0xffffffffu, sum, o);
            nv  += __shfl_xor_sync(0xffffffffu, nv,  o);
        }
        if (tid == 0) {
            float loss = 0.0f;
            if (nv > 0.0f) loss = -sum / fmaxf(nv, 1.0f) * TEMPF;
            if (!isfinite(loss)) loss = 0.0f;
            out[0] = loss;
        }
    }
}

// ---------------------------------------------------------------------------
extern "C" void kernel_launch(void* const* d_in, const int* in_sizes, int n_in,
                              void* d_out, int out_size) {
    const float* feat = (const float*)d_in[0];
    const int*   pl   = (const int*)d_in[1];
    const int*   sl   = (const int*)d_in[2];
    float* out = (float*)d_out;

    cudaFuncSetAttribute(pair_kernel, cudaFuncAttributeMaxDynamicSharedMemorySize, SMEM_REQ);

    norm_kernel<<<NP / 8, 256>>>(feat);
    pair_kernel<<<2 * NSTRIPES, 256, SMEM_REQ>>>(pl, sl);
    finalize_kernel<<<1, 1024>>>(out);
}

// round 5
// speedup vs baseline: 7.4339x; 1.6966x over previous
#include <cuda_runtime.h>
#include <cuda_bf16.h>
#include <math.h>
#include <stdint.h>

#define NP   8192
#define DIM  128
#define NSTR 64               // 64 stripes of 128 rows
#define NTILES_TRI 2080       // 64*65/2
#define NCTA 148

#define KLN2F  6.1996966f             // (1/(sqrt_c*T)) * ln2
#define KFULLF 8.944271909999159f     // 1/(sqrt_c*T)
#define TEMPF  0.5f

#define LDS_ROW 272           // 128 bf16 + 8 pad = 272B rows

#define OFF_A0 0
#define OFF_A1 34816
#define OFF_B0 69632
#define OFF_B1 104448
#define SMEM_REQ 139264

__device__ __nv_bfloat16 g_fb[NP * DIM];   // normalized features, bf16
__device__ int    g_lab[NP];               // packed (pl<<16)|sl
__device__ float4 g_stats[NP];             // x=T(=pos+neg), y=P, z=Sum adc(pos), w=Np

// ---------------- PTX helpers (base sm_103-safe) ----------------
__device__ __forceinline__ uint32_t smem_u32(const void* p) {
    uint32_t a;
    asm("{ .reg .u64 t; cvta.to.shared.u64 t, %1; cvt.u32.u64 %0, t; }" : "=r"(a) : "l"(p));
    return a;
}
__device__ __forceinline__ float f_sqrt(float x){float r;asm("sqrt.approx.f32 %0,%1;":"=f"(r):"f"(x));return r;}
__device__ __forceinline__ float f_lg2(float x){float r;asm("lg2.approx.f32 %0,%1;":"=f"(r):"f"(x));return r;}
__device__ __forceinline__ float f_ex2(float x){float r;asm("ex2.approx.f32 %0,%1;":"=f"(r):"f"(x));return r;}

__device__ __forceinline__ void cp16(uint32_t dst, const void* src) {
    asm volatile("cp.async.cg.shared.global [%0], [%1], 16;" :: "r"(dst), "l"(src) : "memory");
}
#define CP_COMMIT() asm volatile("cp.async.commit_group;" ::: "memory")
#define CP_WAIT(n)  asm volatile("cp.async.wait_group %0;" :: "n"(n) : "memory")

__device__ __forceinline__ void ldsm4(uint32_t& r0, uint32_t& r1, uint32_t& r2, uint32_t& r3,
                                      uint32_t addr) {
    asm volatile("ldmatrix.sync.aligned.m8n8.x4.shared.b16 {%0,%1,%2,%3}, [%4];"
                 : "=r"(r0), "=r"(r1), "=r"(r2), "=r"(r3) : "r"(addr));
}
__device__ __forceinline__ void mma16816(float* c, const uint32_t* a, const uint32_t* b) {
    asm volatile(
        "mma.sync.aligned.m16n8k16.row.col.f32.bf16.bf16.f32 "
        "{%0,%1,%2,%3}, {%4,%5,%6,%7}, {%8,%9}, {%0,%1,%2,%3};"
        : "+f"(c[0]), "+f"(c[1]), "+f"(c[2]), "+f"(c[3])
        : "r"(a[0]), "r"(a[1]), "r"(a[2]), "r"(a[3]), "r"(b[0]), "r"(b[1]));
}

// ---------------------------------------------------------------------------
// Normalize rows -> bf16, pack labels, zero stats.
__global__ void norm_kernel(const float* __restrict__ feat,
                            const int* __restrict__ pl, const int* __restrict__ sl) {
    int row  = blockIdx.x * 8 + (threadIdx.x >> 5);
    int lane = threadIdx.x & 31;
    float4 v = ((const float4*)(feat + row * DIM))[lane];
    float s = v.x*v.x + v.y*v.y + v.z*v.z + v.w*v.w;
    #pragma unroll
    for (int o = 16; o; o >>= 1) s += __shfl_xor_sync(0xffffffffu, s, o);
    float inv = 1.0f / fmaxf(sqrtf(s), 1e-12f);
    __nv_bfloat162 p0 = __floats2bfloat162_rn(v.x*inv, v.y*inv);
    __nv_bfloat162 p1 = __floats2bfloat162_rn(v.z*inv, v.w*inv);
    uint2 w;
    w.x = *reinterpret_cast<uint32_t*>(&p0);
    w.y = *reinterpret_cast<uint32_t*>(&p1);
    ((uint2*)g_fb)[row * 32 + lane] = w;
    if (lane == 0) g_lab[row] = (pl[row] << 16) | (sl[row] & 0xFFFF);
    if (threadIdx.x < 8) g_stats[blockIdx.x * 8 + threadIdx.x] = make_float4(0.f,0.f,0.f,0.f);
}

// cp.async one 128x128 bf16 tile (256B GMEM rows) into padded SMEM
__device__ __forceinline__ void cp_tile(uint32_t udst, const char* gsrc, int tid) {
    #pragma unroll
    for (int it = 0; it < 8; it++) {
        int idx = tid + it * 256;
        int row = idx >> 4;
        int ch  = idx & 15;
        cp16(udst + row * LDS_ROW + ch * 16, gsrc + row * 256 + ch * 16);
    }
}

// ---------------------------------------------------------------------------
__global__ void __launch_bounds__(256, 1)
pair_kernel() {
    extern __shared__ __align__(16) char sm[];
    const uint32_t ub = smem_u32(sm);

    const int tid  = threadIdx.x;
    const int wid  = tid >> 5;
    const int lane = tid & 31;
    const int wm   = wid & 3;
    const int wn   = wid >> 2;
    const char* gsrc = (const char*)g_fb;

    // tile range for this CTA over the 2080 upper-triangle tiles
    const int cta = blockIdx.x;
    const int t0  = cta * 14 + (cta < 8 ? cta : 8);
    const int tend = t0 + 14 + (cta < 8 ? 1 : 0);

    int I = 0, base = 0;
    while (base + (NSTR - I) <= t0) { base += NSTR - I; I++; }
    int J = I + (t0 - base);

    cp_tile(ub + OFF_A0, gsrc + (size_t)I * 128 * 256, tid);
    cp_tile(ub + OFF_B0, gsrc + (size_t)J * 128 * 256, tid);
    CP_COMMIT();
    int abuf = 0, bbuf = 0;

    // ldmatrix lane offsets
    const int g  = lane >> 3;
    const int lr = lane & 7;
    uint32_t aoff[2], boff[4];
    #pragma unroll
    for (int a = 0; a < 2; a++)
        aoff[a] = (uint32_t)((wm * 32 + a * 16 + (g & 1) * 8 + lr) * LDS_ROW + (g >> 1) * 16);
    #pragma unroll
    for (int p = 0; p < 4; p++)
        boff[p] = (uint32_t)((wn * 64 + p * 16 + (g >> 1) * 8 + lr) * LDS_ROW + (g & 1) * 16);

    // row identity for current stripe I
    int grow[4], pk[4];
    {
        #pragma unroll
        for (int rr = 0; rr < 4; rr++) {
            grow[rr] = I * 128 + wm * 32 + (rr >> 1) * 16 + (rr & 1) * 8 + (lane >> 2);
            pk[rr]   = g_lab[grow[rr]];
        }
    }
    float T[4] = {0,0,0,0}, P[4] = {0,0,0,0}, Ap[4] = {0,0,0,0};
    int Np[4] = {0,0,0,0};

    const int2* glab2 = (const int2*)g_lab;

    for (int t = t0; t < tend; t++) {
        int In = I, Jn = J + 1;
        if (Jn == NSTR) { In = I + 1; Jn = In; }
        const bool last = (t + 1 >= tend);

        if (t > t0) __syncthreads();       // all warps done with buffers being overwritten
        if (!last) {
            cp_tile(ub + (bbuf ? OFF_B0 : OFF_B1), gsrc + (size_t)Jn * 128 * 256, tid);
            if (In != I)
                cp_tile(ub + (abuf ? OFF_A0 : OFF_A1), gsrc + (size_t)In * 128 * 256, tid);
            CP_COMMIT();
            CP_WAIT(1);
        } else {
            CP_WAIT(0);
        }
        __syncthreads();

        const uint32_t uA = ub + (abuf ? OFF_A1 : OFF_A0);
        const uint32_t uB = ub + (bbuf ? OFF_B1 : OFF_B0);

        float acc[2][8][4];
        #pragma unroll
        for (int a = 0; a < 2; a++)
            #pragma unroll
            for (int b = 0; b < 8; b++)
                #pragma unroll
                for (int j = 0; j < 4; j++) acc[a][b][j] = 0.0f;

        #pragma unroll
        for (int ks = 0; ks < 8; ks++) {
            const uint32_t kb = (uint32_t)(ks * 32);
            uint32_t af[2][4], bf[8][2];
            #pragma unroll
            for (int a = 0; a < 2; a++)
                ldsm4(af[a][0], af[a][1], af[a][2], af[a][3], uA + aoff[a] + kb);
            #pragma unroll
            for (int p = 0; p < 4; p++)
                ldsm4(bf[2*p][0], bf[2*p][1], bf[2*p+1][0], bf[2*p+1][1], uB + boff[p] + kb);
            #pragma unroll
            for (int a = 0; a < 2; a++)
                #pragma unroll
                for (int b = 0; b < 8; b++)
                    mma16816(acc[a][b], af[a], bf[b]);
        }

        // ---- epilogue ----
        const int  jt = J * 128;
        const bool offdiag = (J != I);
        #pragma unroll
        for (int b = 0; b < 8; b++) {
            const int li  = wn * 64 + b * 8 + ((lane & 3) << 1);
            const int2 pk2 = glab2[(jt + li) >> 1];
            float Tc0=0.f,Pc0=0.f,Ac0=0.f, Tc1=0.f,Pc1=0.f,Ac1=0.f;
            int Nc0=0, Nc1=0;
            #pragma unroll
            for (int a = 0; a < 2; a++) {
                #pragma unroll
                for (int j = 0; j < 4; j++) {
                    const int rr  = a * 2 + (j >> 1);
                    const int col = jt + li + (j & 1);
                    float s  = acc[a][b][j];
                    float q  = fmaf(-11.025f, s, 10.025f);
                    float t2 = fmaf(s, s, q);                 // (1-s)(10.025-s)
                    float arg = fmaxf(0.01f * t2, 0.0f);
                    float x  = f_sqrt(arg);                   // sqrt_c*sqrt(num)
                    float dn = fmaf(-0.1f, s, 1.0025f);
                    float L2 = f_lg2(dn + x) - f_lg2(dn - x); // lg2((1+nd)/(1-nd))
                    float e  = f_ex2(-KFULLF * L2);           // exp(logits), m=0
                    int pkj  = (j & 1) ? pk2.y : pk2.x;
                    unsigned dx = (unsigned)(pk[rr] ^ pkj);
                    bool sp  = ((dx >> 16) == 0u) | ((dx & 0xFFFFu) == 0u);
                    bool dg  = (col == grow[rr]);
                    bool pos = sp && !dg;
                    float eall = dg  ? 0.0f : e;
                    float epos = pos ? e    : 0.0f;
                    float lpos = pos ? L2   : 0.0f;
                    T[rr] += eall; P[rr] += epos; Ap[rr] += lpos; Np[rr] += (int)pos;
                    if (j & 1) { Tc1 += eall; Pc1 += epos; Ac1 += lpos; Nc1 += (int)pos; }
                    else       { Tc0 += eall; Pc0 += epos; Ac0 += lpos; Nc0 += (int)pos; }
                }
            }
            if (offdiag) {   // mirror into rows of stripe J
                #pragma unroll
                for (int o = 4; o <= 16; o <<= 1) {
                    Tc0 += __shfl_xor_sync(0xffffffffu, Tc0, o);
                    Pc0 += __shfl_xor_sync(0xffffffffu, Pc0, o);
                    Ac0 += __shfl_xor_sync(0xffffffffu, Ac0, o);
                    Nc0 += __shfl_xor_sync(0xffffffffu, Nc0, o);
                    Tc1 += __shfl_xor_sync(0xffffffffu, Tc1, o);
                    Pc1 += __shfl_xor_sync(0xffffffffu, Pc1, o);
                    Ac1 += __shfl_xor_sync(0xffffffffu, Ac1, o);
                    Nc1 += __shfl_xor_sync(0xffffffffu, Nc1, o);
                }
                if (lane < 4) {
                    float* d0 = (float*)&g_stats[jt + li];
                    atomicAdd(d0 + 0, Tc0);
                    atomicAdd(d0 + 1, Pc0);
                    atomicAdd(d0 + 2, -KLN2F * Ac0);
                    atomicAdd(d0 + 3, (float)Nc0);
                    float* d1 = (float*)&g_stats[jt + li + 1];
                    atomicAdd(d1 + 0, Tc1);
                    atomicAdd(d1 + 1, Pc1);
                    atomicAdd(d1 + 2, -KLN2F * Ac1);
                    atomicAdd(d1 + 3, (float)Nc1);
                }
            }
        }

        // row-stat flush on stripe change / end
        if (last || In != I) {
            #pragma unroll
            for (int rr = 0; rr < 4; rr++) {
                float tr = T[rr], pr = P[rr], ar = Ap[rr];
                int   nr = Np[rr];
                #pragma unroll
                for (int o = 1; o <= 2; o <<= 1) {
                    tr += __shfl_xor_sync(0xffffffffu, tr, o);
                    pr += __shfl_xor_sync(0xffffffffu, pr, o);
                    ar += __shfl_xor_sync(0xffffffffu, ar, o);
                    nr += __shfl_xor_sync(0xffffffffu, nr, o);
                }
                if ((lane & 3) == 0) {
                    float* d = (float*)&g_stats[grow[rr]];
                    atomicAdd(d + 0, tr);
                    atomicAdd(d + 1, pr);
                    atomicAdd(d + 2, -KLN2F * ar);
                    atomicAdd(d + 3, (float)nr);
                }
                T[rr] = 0.f; P[rr] = 0.f; Ap[rr] = 0.f; Np[rr] = 0;
            }
            if (!last && In != I) {
                abuf ^= 1;
                #pragma unroll
                for (int rr = 0; rr < 4; rr++) {
                    grow[rr] = In * 128 + wm * 32 + (rr >> 1) * 16 + (rr & 1) * 8 + (lane >> 2);
                    pk[rr]   = g_lab[grow[rr]];
                }
            }
        }
        if (!last) { I = In; J = Jn; bbuf ^= 1; }
    }
}

// ---------------------------------------------------------------------------
__global__ void finalize_kernel(float* __restrict__ out) {
    __shared__ float ssum[32], scnt[32];
    int tid = threadIdx.x;  // 1024
    float sum = 0.0f, nv = 0.0f;
    for (int i = tid; i < NP; i += 1024) {
        float4 st = g_stats[i];   // x=T, y=P, z=SumAdc, w=Np
        if (st.w > 0.0f) {
            float den = st.x + 1e-8f;
            sum += (st.z - st.w * __logf(den)) / st.w;
            nv  += 1.0f;
        }
    }
    #pragma unroll
    for (int o = 16; o; o >>= 1) {
        sum += __shfl_xor_sync(0xffffffffu, sum, o);
        nv  += __shfl_xor_sync(0xffffffffu, nv,  o);
    }
    if ((tid & 31) == 0) { ssum[tid >> 5] = sum; scnt[tid >> 5] = nv; }
    __syncthreads();
    if (tid < 32) {
        sum = ssum[tid]; nv = scnt[tid];
        #pragma unroll
        for (int o = 16; o; o >>= 1) {
            sum += __shfl_xor_sync(0xffffffffu, sum, o);
            nv  += __shfl_xor_sync(0xffffffffu, nv,  o);
        }
        if (tid == 0) {
            float loss = 0.0f;
            if (nv > 0.0f) loss = -sum / fmaxf(nv, 1.0f) * TEMPF;
            if (!isfinite(loss)) loss = 0.0f;
            out[0] = loss;
        }
    }
}

// ---------------------------------------------------------------------------
extern "C" void kernel_launch(void* const* d_in, const int* in_sizes, int n_in,
                              void* d_out, int out_size) {
    const float* feat = (const float*)d_in[0];
    const int*   pl   = (const int*)d_in[1];
    const int*   sl   = (const int*)d_in[2];
    float* out = (float*)d_out;

    cudaFuncSetAttribute(pair_kernel, cudaFuncAttributeMaxDynamicSharedMemorySize, SMEM_REQ);

    norm_kernel<<<NP / 8, 256>>>(feat, pl, sl);
    pair_kernel<<<NCTA, 256, SMEM_REQ>>>();
    finalize_kernel<<<1, 1024>>>(out);
}

// round 7
// speedup vs baseline: 8.1893x; 1.1016x over previous
#include <cuda_runtime.h>
#include <cuda_bf16.h>
#include <math.h>
#include <stdint.h>

#define NP   8192
#define DIM  128
#define NSTR 64               // 64 stripes of 128 rows
#define NCTA 148
#define NTHR 512

#define KLN2F  6.1996966f             // (1/(sqrt_c*T)) * ln2
#define KFULLF 8.944271909999159f     // 1/(sqrt_c*T)
#define TEMPF  0.5f

#define LDS_ROW 272           // 128 bf16 + 8 pad = 272B rows

#define OFF_A0 0
#define OFF_A1 34816
#define OFF_B0 69632
#define OFF_B1 104448
#define SMEM_REQ 139264

__device__ __nv_bfloat16 g_fb[NP * DIM];   // normalized features, bf16
__device__ int    g_lab[NP];               // packed (pl<<16)|sl
__device__ float4 g_stats[NP];             // x=T, y=P, z=Sum adc(pos), w=Np

// ---------------- PTX helpers (base sm_103-safe) ----------------
__device__ __forceinline__ uint32_t smem_u32(const void* p) {
    uint32_t a;
    asm("{ .reg .u64 t; cvta.to.shared.u64 t, %1; cvt.u32.u64 %0, t; }" : "=r"(a) : "l"(p));
    return a;
}
__device__ __forceinline__ float f_sqrt(float x){float r;asm("sqrt.approx.f32 %0,%1;":"=f"(r):"f"(x));return r;}
__device__ __forceinline__ float f_lg2(float x){float r;asm("lg2.approx.f32 %0,%1;":"=f"(r):"f"(x));return r;}
__device__ __forceinline__ float f_ex2(float x){float r;asm("ex2.approx.f32 %0,%1;":"=f"(r):"f"(x));return r;}

__device__ __forceinline__ void cp16(uint32_t dst, const void* src) {
    asm volatile("cp.async.cg.shared.global [%0], [%1], 16;" :: "r"(dst), "l"(src) : "memory");
}
#define CP_COMMIT() asm volatile("cp.async.commit_group;" ::: "memory")
#define CP_WAIT(n)  asm volatile("cp.async.wait_group %0;" :: "n"(n) : "memory")

__device__ __forceinline__ void ldsm4(uint32_t& r0, uint32_t& r1, uint32_t& r2, uint32_t& r3,
                                      uint32_t addr) {
    asm volatile("ldmatrix.sync.aligned.m8n8.x4.shared.b16 {%0,%1,%2,%3}, [%4];"
                 : "=r"(r0), "=r"(r1), "=r"(r2), "=r"(r3) : "r"(addr));
}
__device__ __forceinline__ void mma16816(float* c, const uint32_t* a, const uint32_t* b) {
    asm volatile(
        "mma.sync.aligned.m16n8k16.row.col.f32.bf16.bf16.f32 "
        "{%0,%1,%2,%3}, {%4,%5,%6,%7}, {%8,%9}, {%0,%1,%2,%3};"
        : "+f"(c[0]), "+f"(c[1]), "+f"(c[2]), "+f"(c[3])
        : "r"(a[0]), "r"(a[1]), "r"(a[2]), "r"(a[3]), "r"(b[0]), "r"(b[1]));
}

// ---------------------------------------------------------------------------
__global__ void norm_kernel(const float* __restrict__ feat,
                            const int* __restrict__ pl, const int* __restrict__ sl) {
    int row  = blockIdx.x * 8 + (threadIdx.x >> 5);
    int lane = threadIdx.x & 31;
    float4 v = ((const float4*)(feat + row * DIM))[lane];
    float s = v.x*v.x + v.y*v.y + v.z*v.z + v.w*v.w;
    #pragma unroll
    for (int o = 16; o; o >>= 1) s += __shfl_xor_sync(0xffffffffu, s, o);
    float inv = 1.0f / fmaxf(sqrtf(s), 1e-12f);
    __nv_bfloat162 p0 = __floats2bfloat162_rn(v.x*inv, v.y*inv);
    __nv_bfloat162 p1 = __floats2bfloat162_rn(v.z*inv, v.w*inv);
    uint2 w;
    w.x = *reinterpret_cast<uint32_t*>(&p0);
    w.y = *reinterpret_cast<uint32_t*>(&p1);
    ((uint2*)g_fb)[row * 32 + lane] = w;
    if (lane == 0) g_lab[row] = (pl[row] << 16) | (sl[row] & 0xFFFF);
    if (threadIdx.x < 8) g_stats[blockIdx.x * 8 + threadIdx.x] = make_float4(0.f,0.f,0.f,0.f);
}

// cp.async one 128x128 bf16 tile (256B GMEM rows) into padded SMEM (512 thr)
__device__ __forceinline__ void cp_tile(uint32_t udst, const char* gsrc, int tid) {
    #pragma unroll
    for (int it = 0; it < 4; it++) {
        int idx = tid + it * NTHR;
        int row = idx >> 4;
        int ch  = idx & 15;
        cp16(udst + row * LDS_ROW + ch * 16, gsrc + row * 256 + ch * 16);
    }
}

// ---------------------------------------------------------------------------
__global__ void __launch_bounds__(NTHR, 1)
pair_kernel() {
    extern __shared__ __align__(16) char sm[];
    const uint32_t ub = smem_u32(sm);

    const int tid  = threadIdx.x;
    const int wid  = tid >> 5;
    const int lane = tid & 31;
    const int wm   = wid & 3;       // row block (32 rows)
    const int wn   = wid >> 2;      // col block (32 cols)
    const char* gsrc = (const char*)g_fb;

    // tile range over the 2080 upper-triangle tiles
    const int cta  = blockIdx.x;
    const int t0   = cta * 14 + (cta < 8 ? cta : 8);
    const int tend = t0 + 14 + (cta < 8 ? 1 : 0);

    int I = 0, base = 0;
    while (base + (NSTR - I) <= t0) { base += NSTR - I; I++; }
    int J = I + (t0 - base);

    cp_tile(ub + OFF_A0, gsrc + (size_t)I * 128 * 256, tid);
    cp_tile(ub + OFF_B0, gsrc + (size_t)J * 128 * 256, tid);
    CP_COMMIT();
    int abuf = 0, bbuf = 0;

    // ldmatrix lane offsets
    const int g  = lane >> 3;
    const int lr = lane & 7;
    uint32_t aoff[2], boff[2];
    #pragma unroll
    for (int a = 0; a < 2; a++)
        aoff[a] = (uint32_t)((wm * 32 + a * 16 + (g & 1) * 8 + lr) * LDS_ROW + (g >> 1) * 16);
    #pragma unroll
    for (int p = 0; p < 2; p++)
        boff[p] = (uint32_t)((wn * 32 + p * 16 + (g >> 1) * 8 + lr) * LDS_ROW + (g & 1) * 16);

    // row identity for current stripe I
    int grow[4], pk[4];
    #pragma unroll
    for (int rr = 0; rr < 4; rr++) {
        grow[rr] = I * 128 + wm * 32 + (rr >> 1) * 16 + (rr & 1) * 8 + (lane >> 2);
        pk[rr]   = g_lab[grow[rr]];
    }
    float T[4] = {0,0,0,0}, P[4] = {0,0,0,0}, Ap[4] = {0,0,0,0};
    int Np[4] = {0,0,0,0};

    const int2* glab2 = (const int2*)g_lab;

    for (int t = t0; t < tend; t++) {
        int In = I, Jn = J + 1;
        if (Jn == NSTR) { In = I + 1; Jn = In; }
        const bool last = (t + 1 >= tend);

        if (t > t0) __syncthreads();
        if (!last) {
            cp_tile(ub + (bbuf ? OFF_B0 : OFF_B1), gsrc + (size_t)Jn * 128 * 256, tid);
            if (In != I)
                cp_tile(ub + (abuf ? OFF_A0 : OFF_A1), gsrc + (size_t)In * 128 * 256, tid);
            CP_COMMIT();
            CP_WAIT(1);
        } else {
            CP_WAIT(0);
        }
        __syncthreads();

        const uint32_t uA = ub + (abuf ? OFF_A1 : OFF_A0);
        const uint32_t uB = ub + (bbuf ? OFF_B1 : OFF_B0);

        float acc[2][4][4];
        #pragma unroll
        for (int a = 0; a < 2; a++)
            #pragma unroll
            for (int b = 0; b < 4; b++)
                #pragma unroll
                for (int j = 0; j < 4; j++) acc[a][b][j] = 0.0f;

        #pragma unroll
        for (int ks = 0; ks < 8; ks++) {
            const uint32_t kb = (uint32_t)(ks * 32);
            uint32_t af[2][4], bf[4][2];
            #pragma unroll
            for (int a = 0; a < 2; a++)
                ldsm4(af[a][0], af[a][1], af[a][2], af[a][3], uA + aoff[a] + kb);
            #pragma unroll
            for (int p = 0; p < 2; p++)
                ldsm4(bf[2*p][0], bf[2*p][1], bf[2*p+1][0], bf[2*p+1][1], uB + boff[p] + kb);
            #pragma unroll
            for (int a = 0; a < 2; a++)
                #pragma unroll
                for (int b = 0; b < 4; b++)
                    mma16816(acc[a][b], af[a], bf[b]);
        }

        // ---- epilogue ----
        const int  jt = J * 128;
        const bool offdiag = (J != I);
        #pragma unroll
        for (int b = 0; b < 4; b++) {
            const int li  = wn * 32 + b * 8 + ((lane & 3) << 1);
            const int2 pk2 = glab2[(jt + li) >> 1];
            float Tc0=0.f,Pc0=0.f,Ac0=0.f, Tc1=0.f,Pc1=0.f,Ac1=0.f;
            int Nc0=0, Nc1=0;
            #pragma unroll
            for (int a = 0; a < 2; a++) {
                #pragma unroll
                for (int j = 0; j < 4; j++) {
                    const int rr  = a * 2 + (j >> 1);
                    const int col = jt + li + (j & 1);
                    float s  = acc[a][b][j];
                    float q  = fmaf(-11.025f, s, 10.025f);
                    float t2 = fmaf(s, s, q);                 // (1-s)(10.025-s)
                    float arg = fmaxf(0.01f * t2, 0.0f);
                    float x  = f_sqrt(arg);                   // sqrt_c*sqrt(num)
                    float dn = fmaf(-0.1f, s, 1.0025f);
                    float L2 = f_lg2(dn + x) - f_lg2(dn - x); // lg2((1+nd)/(1-nd))
                    float e  = f_ex2(-KFULLF * L2);           // exp(logits), m=0
                    int pkj  = (j & 1) ? pk2.y : pk2.x;
                    unsigned dx = (unsigned)(pk[rr] ^ pkj);
                    bool sp  = ((dx >> 16) == 0u) | ((dx & 0xFFFFu) == 0u);
                    bool dg  = (col == grow[rr]);
                    bool pos = sp && !dg;
                    float eall = dg  ? 0.0f : e;
                    float epos = pos ? e    : 0.0f;
                    float lpos = pos ? L2   : 0.0f;
                    T[rr] += eall; P[rr] += epos; Ap[rr] += lpos; Np[rr] += (int)pos;
                    if (j & 1) { Tc1 += eall; Pc1 += epos; Ac1 += lpos; Nc1 += (int)pos; }
                    else       { Tc0 += eall; Pc0 += epos; Ac0 += lpos; Nc0 += (int)pos; }
                }
            }
            if (offdiag) {   // mirror into rows of stripe J
                #pragma unroll
                for (int o = 4; o <= 16; o <<= 1) {
                    Tc0 += __shfl_xor_sync(0xffffffffu, Tc0, o);
                    Pc0 += __shfl_xor_sync(0xffffffffu, Pc0, o);
                    Ac0 += __shfl_xor_sync(0xffffffffu, Ac0, o);
                    Nc0 += __shfl_xor_sync(0xffffffffu, Nc0, o);
                    Tc1 += __shfl_xor_sync(0xffffffffu, Tc1, o);
                    Pc1 += __shfl_xor_sync(0xffffffffu, Pc1, o);
                    Ac1 += __shfl_xor_sync(0xffffffffu, Ac1, o);
                    Nc1 += __shfl_xor_sync(0xffffffffu, Nc1, o);
                }
                if (lane < 4) {
                    float* d0 = (float*)&g_stats[jt + li];
                    atomicAdd(d0 + 0, Tc0);
                    atomicAdd(d0 + 1, Pc0);
                    atomicAdd(d0 + 2, -KLN2F * Ac0);
                    atomicAdd(d0 + 3, (float)Nc0);
                    float* d1 = (float*)&g_stats[jt + li + 1];
                    atomicAdd(d1 + 0, Tc1);
                    atomicAdd(d1 + 1, Pc1);
                    atomicAdd(d1 + 2, -KLN2F * Ac1);
                    atomicAdd(d1 + 3, (float)Nc1);
                }
            }
        }

        // row-stat flush on stripe change / end
        if (last || In != I) {
            #pragma unroll
            for (int rr = 0; rr < 4; rr++) {
                float tr = T[rr], pr = P[rr], ar = Ap[rr];
                int   nr = Np[rr];
                #pragma unroll
                for (int o = 1; o <= 2; o <<= 1) {
                    tr += __shfl_xor_sync(0xffffffffu, tr, o);
                    pr += __shfl_xor_sync(0xffffffffu, pr, o);
                    ar += __shfl_xor_sync(0xffffffffu, ar, o);
                    nr += __shfl_xor_sync(0xffffffffu, nr, o);
                }
                if ((lane & 3) == 0) {
                    float* d = (float*)&g_stats[grow[rr]];
                    atomicAdd(d + 0, tr);
                    atomicAdd(d + 1, pr);
                    atomicAdd(d + 2, -KLN2F * ar);
                    atomicAdd(d + 3, (float)nr);
                }
                T[rr] = 0.f; P[rr] = 0.f; Ap[rr] = 0.f; Np[rr] = 0;
            }
            if (!last && In != I) {
                abuf ^= 1;
                #pragma unroll
                for (int rr = 0; rr < 4; rr++) {
                    grow[rr] = In * 128 + wm * 32 + (rr >> 1) * 16 + (rr & 1) * 8 + (lane >> 2);
                    pk[rr]   = g_lab[grow[rr]];
                }
            }
        }
        if (!last) { I = In; J = Jn; bbuf ^= 1; }
    }
}

// ---------------------------------------------------------------------------
__global__ void finalize_kernel(float* __restrict__ out) {
    __shared__ float ssum[32], scnt[32];
    int tid = threadIdx.x;  // 1024
    float sum = 0.0f, nv = 0.0f;
    for (int i = tid; i < NP; i += 1024) {
        float4 st = g_stats[i];   // x=T, y=P, z=SumAdc, w=Np
        if (st.w > 0.0f) {
            float den = st.x + 1e-8f;
            sum += (st.z - st.w * __logf(den)) / st.w;
            nv  += 1.0f;
        }
    }
    #pragma unroll
    for (int o = 16; o; o >>= 1) {
        sum += __shfl_xor_sync(0xffffffffu, sum, o);
        nv  += __shfl_xor_sync(0xffffffffu, nv,  o);
    }
    if ((tid & 31) == 0) { ssum[tid >> 5] = sum; scnt[tid >> 5] = nv; }
    __syncthreads();
    if (tid < 32) {
        sum = ssum[tid]; nv = scnt[tid];
        #pragma unroll
        for (int o = 16; o; o >>= 1) {
            sum += __shfl_xor_sync(0xffffffffu, sum, o);
            nv  += __shfl_xor_sync(0xffffffffu, nv,  o);
        }
        if (tid == 0) {
            float loss = 0.0f;
            if (nv > 0.0f) loss = -sum / fmaxf(nv, 1.0f) * TEMPF;
            if (!isfinite(loss)) loss = 0.0f;
            out[0] = loss;
        }
    }
}

// ---------------------------------------------------------------------------
extern "C" void kernel_launch(void* const* d_in, const int* in_sizes, int n_in,
                              void* d_out, int out_size) {
    const float* feat = (const float*)d_in[0];
    const int*   pl   = (const int*)d_in[1];
    const int*   sl   = (const int*)d_in[2];
    float* out = (float*)d_out;

    cudaFuncSetAttribute(pair_kernel, cudaFuncAttributeMaxDynamicSharedMemorySize, SMEM_REQ);

    norm_kernel<<<NP / 8, 256>>>(feat, pl, sl);
    pair_kernel<<<NCTA, NTHR, SMEM_REQ>>>();
    finalize_kernel<<<1, 1024>>>(out);
}

// round 8
// speedup vs baseline: 9.9500x; 1.2150x over previous
#include <cuda_runtime.h>
#include <cuda_bf16.h>
#include <math.h>
#include <stdint.h>

#define NP   8192
#define DIM  128
#define NSTR 64               // 64 stripes of 128 rows
#define NCTA 148
#define NTHR 512

#define KLN2F  6.1996966f             // ln2/(sqrt_c*T)
#define KFULLF 8.944271909999159f     // 1/(sqrt_c*T)
#define TEMPF  0.5f
#define LG09   -0.14801175f           // lg2(0.9025)
// Taylor of lg2(1+d), d in [-0.0975, 0.1025]
#define PC1  1.44269504f
#define PC2 -0.72134752f
#define PC3  0.48089835f
#define PC4 -0.36067376f

#define LDS_ROW 272           // 128 bf16 + 8 pad

#define OFF_A0 0
#define OFF_A1 34816
#define OFF_B0 69632
#define OFF_B1 104448
#define OFF_B2 139264
#define SMEM_REQ 174080

__device__ __nv_bfloat16 g_fb[NP * DIM];   // normalized features, bf16
__device__ int    g_lab[NP];               // packed (pl<<16)|sl
__device__ float2 g_stats2[NP];            // x=T (sum exp, excl diag), y=Sum L2(pos)

// ---------------- PTX helpers (base sm_103-safe) ----------------
__device__ __forceinline__ uint32_t smem_u32(const void* p) {
    uint32_t a;
    asm("{ .reg .u64 t; cvta.to.shared.u64 t, %1; cvt.u32.u64 %0, t; }" : "=r"(a) : "l"(p));
    return a;
}
__device__ __forceinline__ float f_sqrt(float x){float r;asm("sqrt.approx.f32 %0,%1;":"=f"(r):"f"(x));return r;}
__device__ __forceinline__ float f_lg2(float x){float r;asm("lg2.approx.f32 %0,%1;":"=f"(r):"f"(x));return r;}
__device__ __forceinline__ float f_ex2(float x){float r;asm("ex2.approx.f32 %0,%1;":"=f"(r):"f"(x));return r;}

__device__ __forceinline__ void cp16(uint32_t dst, const void* src) {
    asm volatile("cp.async.cg.shared.global [%0], [%1], 16;" :: "r"(dst), "l"(src) : "memory");
}
#define CP_COMMIT() asm volatile("cp.async.commit_group;" ::: "memory")
#define CP_WAIT(n)  asm volatile("cp.async.wait_group %0;" :: "n"(n) : "memory")

__device__ __forceinline__ void ldsm4(uint32_t& r0, uint32_t& r1, uint32_t& r2, uint32_t& r3,
                                      uint32_t addr) {
    asm volatile("ldmatrix.sync.aligned.m8n8.x4.shared.b16 {%0,%1,%2,%3}, [%4];"
                 : "=r"(r0), "=r"(r1), "=r"(r2), "=r"(r3) : "r"(addr));
}
__device__ __forceinline__ void mma16816(float* c, const uint32_t* a, const uint32_t* b) {
    asm volatile(
        "mma.sync.aligned.m16n8k16.row.col.f32.bf16.bf16.f32 "
        "{%0,%1,%2,%3}, {%4,%5,%6,%7}, {%8,%9}, {%0,%1,%2,%3};"
        : "+f"(c[0]), "+f"(c[1]), "+f"(c[2]), "+f"(c[3])
        : "r"(a[0]), "r"(a[1]), "r"(a[2]), "r"(a[3]), "r"(b[0]), "r"(b[1]));
}

// ---------------------------------------------------------------------------
__global__ void norm_kernel(const float* __restrict__ feat,
                            const int* __restrict__ pl, const int* __restrict__ sl) {
    int row  = blockIdx.x * 8 + (threadIdx.x >> 5);
    int lane = threadIdx.x & 31;
    float4 v = ((const float4*)(feat + row * DIM))[lane];
    float s = v.x*v.x + v.y*v.y + v.z*v.z + v.w*v.w;
    #pragma unroll
    for (int o = 16; o; o >>= 1) s += __shfl_xor_sync(0xffffffffu, s, o);
    float inv = 1.0f / fmaxf(sqrtf(s), 1e-12f);
    __nv_bfloat162 p0 = __floats2bfloat162_rn(v.x*inv, v.y*inv);
    __nv_bfloat162 p1 = __floats2bfloat162_rn(v.z*inv, v.w*inv);
    uint2 w;
    w.x = *reinterpret_cast<uint32_t*>(&p0);
    w.y = *reinterpret_cast<uint32_t*>(&p1);
    ((uint2*)g_fb)[row * 32 + lane] = w;
    if (lane == 0) g_lab[row] = (pl[row] << 16) | (sl[row] & 0xFFFF);
    if (threadIdx.x < 8) g_stats2[blockIdx.x * 8 + threadIdx.x] = make_float2(0.f, 0.f);
}

// cp.async one 128x128 bf16 tile into padded SMEM (512 thr)
__device__ __forceinline__ void cp_tile(uint32_t udst, const char* gsrc, int tid) {
    #pragma unroll
    for (int it = 0; it < 4; it++) {
        int idx = tid + it * NTHR;
        int row = idx >> 4;
        int ch  = idx & 15;
        cp16(udst + row * LDS_ROW + ch * 16, gsrc + row * 256 + ch * 16);
    }
}

// ---------------------------------------------------------------------------
__global__ void __launch_bounds__(NTHR, 1)
pair_kernel() {
    extern __shared__ __align__(16) char sm[];
    const uint32_t ub = smem_u32(sm);
    const uint32_t boffs[3] = {ub + OFF_B0, ub + OFF_B1, ub + OFF_B2};

    const int tid  = threadIdx.x;
    const int wid  = tid >> 5;
    const int lane = tid & 31;
    const int wm   = wid & 3;
    const int wn   = wid >> 2;
    const char* gsrc = (const char*)g_fb;

    const int cta  = blockIdx.x;
    const int t0   = cta * 14 + (cta < 8 ? cta : 8);
    const int tend = t0 + 14 + (cta < 8 ? 1 : 0);

    int I = 0, base = 0;
    while (base + (NSTR - I) <= t0) { base += NSTR - I; I++; }
    int J = I + (t0 - base);

    cp_tile(ub + OFF_A0, gsrc + (size_t)I * 128 * 256, tid);
    cp_tile(boffs[0],    gsrc + (size_t)J * 128 * 256, tid);
    CP_COMMIT();
    int abuf = 0;

    // ldmatrix lane offsets
    const int g  = lane >> 3;
    const int lr = lane & 7;
    uint32_t aoff[2], boff[2];
    #pragma unroll
    for (int a = 0; a < 2; a++)
        aoff[a] = (uint32_t)((wm * 32 + a * 16 + (g & 1) * 8 + lr) * LDS_ROW + (g >> 1) * 16);
    #pragma unroll
    for (int p = 0; p < 2; p++)
        boff[p] = (uint32_t)((wn * 32 + p * 16 + (g >> 1) * 8 + lr) * LDS_ROW + (g & 1) * 16);

    int grow[4], pk[4];
    #pragma unroll
    for (int rr = 0; rr < 4; rr++) {
        grow[rr] = I * 128 + wm * 32 + (rr >> 1) * 16 + (rr & 1) * 8 + (lane >> 2);
        pk[rr]   = g_lab[grow[rr]];
    }
    float T[4] = {0,0,0,0}, Ap[4] = {0,0,0,0};

    const int2* glab2 = (const int2*)g_lab;

    for (int t = t0; t < tend; t++) {
        int In = I, Jn = J + 1;
        if (Jn == NSTR) { In = I + 1; Jn = In; }
        const bool last = (t + 1 >= tend);
        const int  slot = (t - t0) % 3;

        if (!last) {
            cp_tile(boffs[(t - t0 + 1) % 3], gsrc + (size_t)Jn * 128 * 256, tid);
            if (In != I)
                cp_tile(ub + (abuf ? OFF_A0 : OFF_A1), gsrc + (size_t)In * 128 * 256, tid);
            CP_COMMIT();
            CP_WAIT(1);
        } else {
            CP_WAIT(0);
        }
        __syncthreads();

        const uint32_t uA = ub + (abuf ? OFF_A1 : OFF_A0);
        const uint32_t uB = boffs[slot];

        float acc[2][4][4];
        #pragma unroll
        for (int a = 0; a < 2; a++)
            #pragma unroll
            for (int b = 0; b < 4; b++)
                #pragma unroll
                for (int j = 0; j < 4; j++) acc[a][b][j] = 0.0f;

        #pragma unroll
        for (int ks = 0; ks < 8; ks++) {
            const uint32_t kb = (uint32_t)(ks * 32);
            uint32_t af[2][4], bf[4][2];
            #pragma unroll
            for (int a = 0; a < 2; a++)
                ldsm4(af[a][0], af[a][1], af[a][2], af[a][3], uA + aoff[a] + kb);
            #pragma unroll
            for (int p = 0; p < 2; p++)
                ldsm4(bf[2*p][0], bf[2*p][1], bf[2*p+1][0], bf[2*p+1][1], uB + boff[p] + kb);
            #pragma unroll
            for (int a = 0; a < 2; a++)
                #pragma unroll
                for (int b = 0; b < 4; b++)
                    mma16816(acc[a][b], af[a], bf[b]);
        }

        // ---- epilogue (SoA-staged per 8-element group) ----
        const int  jt = J * 128;
        const bool offdiag = (J != I);
        #pragma unroll
        for (int b = 0; b < 4; b++) {
            const int li  = wn * 32 + b * 8 + ((lane & 3) << 1);
            const int2 pk2 = glab2[(jt + li) >> 1];

            float s8[8], sq8[8], l18[8], L28[8], e8[8];
            #pragma unroll
            for (int i = 0; i < 8; i++) s8[i] = acc[i >> 2][b][i & 3];

            #pragma unroll
            for (int i = 0; i < 8; i++) {          // stage 1: sqrt
                float q  = fmaf(-11.025f, s8[i], 10.025f);
                float t2 = fmaf(s8[i], s8[i], q);
                sq8[i] = f_sqrt(fmaxf(t2, 0.0f));
            }
            #pragma unroll
            for (int i = 0; i < 8; i++) {          // stage 2: lg2
                float dn  = fmaf(-0.1f, s8[i], 1.0025f);
                l18[i] = f_lg2(fmaf(0.1f, sq8[i], dn));
            }
            #pragma unroll
            for (int i = 0; i < 8; i++) {          // stage 3: poly + ex2
                float d  = fmaf(-0.1f, s8[i], 0.0025f);   // dn - 1
                float in3 = fmaf(d, PC4, PC3);
                float in2 = fmaf(d, in3, PC2);
                float in1 = fmaf(d, in2, PC1);
                float pc  = fmaf(d, in1, LG09);           // lg2(0.9025*dn)
                float L2  = fmaf(2.0f, l18[i], -pc);
                L28[i] = L2;
                e8[i]  = f_ex2(-KFULLF * L2);
            }

            if (offdiag) {
                float Tc0 = 0.f, Ac0 = 0.f, Tc1 = 0.f, Ac1 = 0.f;
                #pragma unroll
                for (int i = 0; i < 8; i++) {
                    const int rr = (i >> 2) * 2 + ((i & 3) >> 1);
                    const int pkj = (i & 1) ? pk2.y : pk2.x;
                    unsigned dx = (unsigned)(pk[rr] ^ pkj);
                    bool sp = (dx < 0x10000u) | ((dx & 0xFFFFu) == 0u);
                    float lpos = sp ? L28[i] : 0.0f;
                    T[rr] += e8[i]; Ap[rr] += lpos;
                    if (i & 1) { Tc1 += e8[i]; Ac1 += lpos; }
                    else       { Tc0 += e8[i]; Ac0 += lpos; }
                }
                #pragma unroll
                for (int o = 4; o <= 16; o <<= 1) {
                    Tc0 += __shfl_xor_sync(0xffffffffu, Tc0, o);
                    Ac0 += __shfl_xor_sync(0xffffffffu, Ac0, o);
                    Tc1 += __shfl_xor_sync(0xffffffffu, Tc1, o);
                    Ac1 += __shfl_xor_sync(0xffffffffu, Ac1, o);
                }
                if (lane < 4) {
                    float* d0 = (float*)&g_stats2[jt + li];
                    atomicAdd(d0 + 0, Tc0);
                    atomicAdd(d0 + 1, Ac0);
                    atomicAdd(d0 + 2, Tc1);   // g_stats2[jt+li+1].x
                    atomicAdd(d0 + 3, Ac1);   // g_stats2[jt+li+1].y
                }
            } else {
                #pragma unroll
                for (int i = 0; i < 8; i++) {
                    const int rr  = (i >> 2) * 2 + ((i & 3) >> 1);
                    const int col = jt + li + (i & 1);
                    const int pkj = (i & 1) ? pk2.y : pk2.x;
                    unsigned dx = (unsigned)(pk[rr] ^ pkj);
                    bool dg = (col == grow[rr]);
                    bool sp = ((dx < 0x10000u) | ((dx & 0xFFFFu) == 0u)) && !dg;
                    T[rr]  += dg ? 0.0f : e8[i];
                    Ap[rr] += sp ? L28[i] : 0.0f;
                }
            }
        }

        // row-stat flush on stripe change / end
        if (last || In != I) {
            #pragma unroll
            for (int rr = 0; rr < 4; rr++) {
                float tr = T[rr], ar = Ap[rr];
                #pragma unroll
                for (int o = 1; o <= 2; o <<= 1) {
                    tr += __shfl_xor_sync(0xffffffffu, tr, o);
                    ar += __shfl_xor_sync(0xffffffffu, ar, o);
                }
                if ((lane & 3) == 0) {
                    float* d = (float*)&g_stats2[grow[rr]];
                    atomicAdd(d + 0, tr);
                    atomicAdd(d + 1, ar);
                }
                T[rr] = 0.f; Ap[rr] = 0.f;
            }
            if (!last && In != I) {
                abuf ^= 1;
                #pragma unroll
                for (int rr = 0; rr < 4; rr++) {
                    grow[rr] = In * 128 + wm * 32 + (rr >> 1) * 16 + (rr & 1) * 8 + (lane >> 2);
                    pk[rr]   = g_lab[grow[rr]];
                }
            }
        }
        if (!last) { I = In; J = Jn; }
    }
}

// ---------------------------------------------------------------------------
// finalize: label histograms (num_pos) + row reduction -> scalar loss
__global__ void finalize_kernel(float* __restrict__ out) {
    __shared__ int hcp[32], hcs[16], hcj[512];
    __shared__ float ssum[32], scnt[32];
    int tid = threadIdx.x;  // 1024
    if (tid < 512) hcj[tid] = 0;
    if (tid < 32)  hcp[tid] = 0;
    if (tid < 16)  hcs[tid] = 0;
    __syncthreads();
    for (int i = tid; i < NP; i += 1024) {
        int pkv = g_lab[i];
        int p = pkv >> 16, s2 = pkv & 0xFFFF;
        atomicAdd(&hcp[p], 1);
        atomicAdd(&hcs[s2], 1);
        atomicAdd(&hcj[p * 16 + s2], 1);
    }
    __syncthreads();

    float sum = 0.0f, nv = 0.0f;
    for (int i = tid; i < NP; i += 1024) {
        int pkv = g_lab[i];
        int p = pkv >> 16, s2 = pkv & 0xFFFF;
        float np = (float)(hcp[p] + hcs[s2] - hcj[p * 16 + s2] - 1);
        float2 st = g_stats2[i];
        if (np > 0.0f) {
            float den = st.x + 1e-8f;
            sum += (-KLN2F * st.y - np * __logf(den)) / np;
            nv  += 1.0f;
        }
    }
    #pragma unroll
    for (int o = 16; o; o >>= 1) {
        sum += __shfl_xor_sync(0xffffffffu, sum, o);
        nv  += __shfl_xor_sync(0xffffffffu, nv,  o);
    }
    if ((tid & 31) == 0) { ssum[tid >> 5] = sum; scnt[tid >> 5] = nv; }
    __syncthreads();
    if (tid < 32) {
        sum = ssum[tid]; nv = scnt[tid];
        #pragma unroll
        for (int o = 16; o; o >>= 1) {
            sum += __shfl_xor_sync(0xffffffffu, sum, o);
            nv  += __shfl_xor_sync(0xffffffffu, nv,  o);
        }
        if (tid == 0) {
            float loss = 0.0f;
            if (nv > 0.0f) loss = -sum / fmaxf(nv, 1.0f) * TEMPF;
            if (!isfinite(loss)) loss = 0.0f;
            out[0] = loss;
        }
    }
}

// ---------------------------------------------------------------------------
extern "C" void kernel_launch(void* const* d_in, const int* in_sizes, int n_in,
                              void* d_out, int out_size) {
    const float* feat = (const float*)d_in[0];
    const int*   pl   = (const int*)d_in[1];
    const int*   sl   = (const int*)d_in[2];
    float* out = (float*)d_out;

    cudaFuncSetAttribute(pair_kernel, cudaFuncAttributeMaxDynamicSharedMemorySize, SMEM_REQ);

    norm_kernel<<<NP / 8, 256>>>(feat, pl, sl);
    pair_kernel<<<NCTA, NTHR, SMEM_REQ>>>();
    finalize_kernel<<<1, 1024>>>(out);
}